// round 12
// baseline (speedup 1.0000x reference)
#include <cuda_runtime.h>
#include <cuda_fp16.h>
#include <cstdint>
#include <math.h>

#define D_MODEL 768
#define D_FF    2048
#define NE      8
#define T_TOK   2048
#define CAP     2048

// ======================= scratch (__device__ globals) =======================
__device__ int   g_count[NE];
__device__ int   g_fill[NE];
__device__ int   g_rows[NE * CAP];
__device__ float g_wts [NE * CAP];
__device__ int   g_topi[T_TOK * 2];
__device__ float g_topw[T_TOK * 2];

__device__ __align__(16) __half g_x16[T_TOK * D_MODEL];
// weights pre-converted to fp16, native [E][K][N] layout
__device__ __align__(16) __half g_wg16[(size_t)NE * D_MODEL * D_FF];
__device__ __align__(16) __half g_wu16[(size_t)NE * D_MODEL * D_FF];
__device__ __align__(16) __half g_wd16[(size_t)NE * D_FF * D_MODEL];
// h = silu(g)*u, fp16: [E][CAP][D_FF]
__device__ __align__(16) __half g_h16[(size_t)NE * CAP * D_FF];

// ======================= helpers =======================
__device__ __forceinline__ uint32_t smem_u32(const void* p) {
    uint32_t a;
    asm("{ .reg .u64 t; cvta.to.shared.u64 t, %1; cvt.u32.u64 %0, t; }" : "=r"(a) : "l"(p));
    return a;
}
__device__ __forceinline__ void ldsm4(uint32_t (&r)[4], uint32_t addr) {
    asm volatile("ldmatrix.sync.aligned.m8n8.x4.shared.b16 {%0,%1,%2,%3}, [%4];"
                 : "=r"(r[0]), "=r"(r[1]), "=r"(r[2]), "=r"(r[3]) : "r"(addr));
}
__device__ __forceinline__ void ldsm4t(uint32_t (&r)[4], uint32_t addr) {
    asm volatile("ldmatrix.sync.aligned.m8n8.x4.trans.shared.b16 {%0,%1,%2,%3}, [%4];"
                 : "=r"(r[0]), "=r"(r[1]), "=r"(r[2]), "=r"(r[3]) : "r"(addr));
}
// fp16 inputs, fp32 accumulate
__device__ __forceinline__ void mma16816(float (&d)[4], const uint32_t (&a)[4],
                                         uint32_t b0, uint32_t b1) {
    asm volatile(
        "mma.sync.aligned.m16n8k16.row.col.f32.f16.f16.f32 "
        "{%0,%1,%2,%3}, {%4,%5,%6,%7}, {%8,%9}, {%0,%1,%2,%3};"
        : "+f"(d[0]), "+f"(d[1]), "+f"(d[2]), "+f"(d[3])
        : "r"(a[0]), "r"(a[1]), "r"(a[2]), "r"(a[3]), "r"(b0), "r"(b1));
}

__device__ __forceinline__ uint32_t pack2h(__half a, __half b) {
    __half2 p = __halves2half2(a, b);
    return *reinterpret_cast<uint32_t*>(&p);
}

// ======================= small kernels =======================
__global__ void k_reset(float* __restrict__ out, int out_n) {
    int i = blockIdx.x * blockDim.x + threadIdx.x;
    if (i < NE) { g_count[i] = 0; g_fill[i] = 0; }
    for (int j = i; j < out_n; j += gridDim.x * blockDim.x) out[j] = 0.0f;
}

__global__ void k_router(const float* __restrict__ x, const float* __restrict__ gw) {
    int t = blockIdx.x * (blockDim.x >> 5) + (threadIdx.x >> 5);
    int lane = threadIdx.x & 31;
    if (t >= T_TOK) return;
    const float* xr = x + (size_t)t * D_MODEL;
    float acc[NE];
#pragma unroll
    for (int e = 0; e < NE; e++) acc[e] = 0.0f;
    for (int d = lane; d < D_MODEL; d += 32) {
        float xv = xr[d];
        const float* g = gw + (size_t)d * NE;
#pragma unroll
        for (int e = 0; e < NE; e++) acc[e] += xv * g[e];
    }
#pragma unroll
    for (int off = 16; off > 0; off >>= 1)
#pragma unroll
        for (int e = 0; e < NE; e++) acc[e] += __shfl_xor_sync(0xFFFFFFFFu, acc[e], off);

    if (lane == 0) {
        int i0 = 0;
#pragma unroll
        for (int e = 1; e < NE; e++) if (acc[e] > acc[i0]) i0 = e;
        int i1 = -1; float b = -1e30f;
#pragma unroll
        for (int e = 0; e < NE; e++) if (e != i0 && acc[e] > b) { b = acc[e]; i1 = e; }
        float w1 = expf(acc[i1] - acc[i0]);
        float s  = 1.0f + w1;
        g_topi[t * 2 + 0] = i0;  g_topw[t * 2 + 0] = 1.0f / s;
        g_topi[t * 2 + 1] = i1;  g_topw[t * 2 + 1] = w1 / s;
        atomicAdd(&g_count[i0], 1);
        atomicAdd(&g_count[i1], 1);
    }
}

__global__ void k_scatter() {
    int idx = blockIdx.x * blockDim.x + threadIdx.x;
    if (idx >= T_TOK * 2) return;
    int e = g_topi[idx];
    int p = atomicAdd(&g_fill[e], 1);
    g_rows[e * CAP + p] = idx >> 1;
    g_wts [e * CAP + p] = g_topw[idx];
}

// vectorized: 4 fp32 -> 4 fp16 per thread
__global__ void k_cvt_x(const float* __restrict__ x) {
    int i = blockIdx.x * blockDim.x + threadIdx.x;
    if (i >= T_TOK * D_MODEL / 4) return;
    float4 f = reinterpret_cast<const float4*>(x)[i];
    reinterpret_cast<uint2*>(g_x16)[i] = make_uint2(
        pack2h(__float2half_rn(f.x), __float2half_rn(f.y)),
        pack2h(__float2half_rn(f.z), __float2half_rn(f.w)));
}

// weights: fp32 -> fp16, vectorized (n4 = elems/4)
__global__ void k_cvt_w(const float* __restrict__ in, __half* __restrict__ o, int n4) {
    int i = blockIdx.x * blockDim.x + threadIdx.x;
    if (i >= n4) return;
    float4 f = reinterpret_cast<const float4*>(in)[i];
    reinterpret_cast<uint2*>(o)[i] = make_uint2(
        pack2h(__float2half_rn(f.x), __float2half_rn(f.y)),
        pack2h(__float2half_rn(f.z), __float2half_rn(f.w)));
}

// ======================= HMMA GEMM kernels =======================
// Tile: M=128 x N=64, K-chunk 32. 256 threads = 8 warps in 4(m) x 2(n).
// A smem row stride 40 fp16 (80B), B 72 fp16 (144B) -> ldmatrix conflict-free.
#define SA 40
#define SB 72

// h = silu(x@Wg) * (x@Wu)   (weights fp16 [k][n], pre-converted)
__global__ void __launch_bounds__(256) k_hmma_gu() {
    int e   = blockIdx.z;
    int cnt = g_count[e];
    int r0  = blockIdx.y * 128;
    if (r0 >= cnt) return;
    int n0  = blockIdx.x * 64;

    __shared__ __half sA[128 * SA];
    __shared__ __half sGh[32 * SB];
    __shared__ __half sUh[32 * SB];

    int tid = threadIdx.x, lane = tid & 31, wid = tid >> 5;
    int wm = wid >> 1, wn = wid & 1;

    // --- loader setup ---
    int arow = tid >> 1, ahalf = tid & 1;
    int slotA = r0 + arow;
    int tok = (slotA < cnt) ? g_rows[e * CAP + slotA] : 0;
    const __half* pA = g_x16 + (size_t)tok * D_MODEL + ahalf * 16;
    __half* dA = sA + arow * SA + ahalf * 16;

    int brow = tid >> 3, bq = tid & 7;      // 32 k-rows x 8 col-quads
    size_t bbase = (size_t)e * D_MODEL * D_FF + (size_t)brow * D_FF + n0 + bq * 8;
    const __half* pG = g_wg16 + bbase;
    const __half* pU = g_wu16 + bbase;
    uint4* dGh = (uint4*)(sGh + brow * SB + bq * 8);
    uint4* dUh = (uint4*)(sUh + brow * SB + bq * 8);

    uint32_t bA  = smem_u32(sA);
    uint32_t bGh = smem_u32(sGh);
    uint32_t bUh = smem_u32(sUh);

    float ag[2][4][4], au[2][4][4];
#pragma unroll
    for (int i = 0; i < 2; i++)
#pragma unroll
        for (int j = 0; j < 4; j++)
#pragma unroll
            for (int q = 0; q < 4; q++) { ag[i][j][q] = 0.0f; au[i][j][q] = 0.0f; }

    for (int c = 0; c < D_MODEL / 32; c++) {      // 24 chunks
        int k0 = c * 32;
        if (c > 0) __syncthreads();
        // A fill: 16 fp16 per thread
        *(uint4*)dA       = *(const uint4*)(pA + k0);
        *(uint4*)(dA + 8) = *(const uint4*)(pA + k0 + 8);
        // B fill: 8 fp16 per matrix (single LDG.128 each)
        *dGh = *(const uint4*)(pG + (size_t)k0 * D_FF);
        *dUh = *(const uint4*)(pU + (size_t)k0 * D_FF);
        __syncthreads();

#pragma unroll
        for (int kk = 0; kk < 32; kk += 16) {
            uint32_t ah[2][4];
#pragma unroll
            for (int mf = 0; mf < 2; mf++) {
                uint32_t ro = wm * 32 + mf * 16 + (lane & 15);
                uint32_t co = kk + (lane >> 4) * 8;
                ldsm4(ah[mf], bA + (ro * SA + co) * 2);
            }
            uint32_t kr = kk + (lane & 7) + ((lane >> 4) & 1) * 8;
            uint32_t ncol = wn * 32 + ((lane >> 3) & 1) * 8;
            // ---- gate ----
            {
                uint32_t bh[4][2], r4[4];
#pragma unroll
                for (int p = 0; p < 2; p++) {
                    uint32_t off = (kr * SB + ncol + p * 16) * 2;
                    ldsm4t(r4, bGh + off);
                    bh[p*2][0] = r4[0]; bh[p*2+1][0] = r4[1]; bh[p*2][1] = r4[2]; bh[p*2+1][1] = r4[3];
                }
#pragma unroll
                for (int mf = 0; mf < 2; mf++)
#pragma unroll
                    for (int nf = 0; nf < 4; nf++)
                        mma16816(ag[mf][nf], ah[mf], bh[nf][0], bh[nf][1]);
            }
            // ---- up ----
            {
                uint32_t bh[4][2], r4[4];
#pragma unroll
                for (int p = 0; p < 2; p++) {
                    uint32_t off = (kr * SB + ncol + p * 16) * 2;
                    ldsm4t(r4, bUh + off);
                    bh[p*2][0] = r4[0]; bh[p*2+1][0] = r4[1]; bh[p*2][1] = r4[2]; bh[p*2+1][1] = r4[3];
                }
#pragma unroll
                for (int mf = 0; mf < 2; mf++)
#pragma unroll
                    for (int nf = 0; nf < 4; nf++)
                        mma16816(au[mf][nf], ah[mf], bh[nf][0], bh[nf][1]);
            }
        }
    }

    // ---- epilogue: h = silu(g)*u -> fp16 ----
    int lr = lane >> 2, lc = (lane & 3) * 2;
#pragma unroll
    for (int mf = 0; mf < 2; mf++)
#pragma unroll
        for (int half = 0; half < 2; half++) {
            int slot = r0 + wm * 32 + mf * 16 + lr + half * 8;
            if (slot >= cnt) continue;
            size_t base = ((size_t)e * CAP + slot) * D_FF + n0 + wn * 32 + lc;
#pragma unroll
            for (int nf = 0; nf < 4; nf++) {
                float g0 = ag[mf][nf][half * 2 + 0], g1 = ag[mf][nf][half * 2 + 1];
                float u0 = au[mf][nf][half * 2 + 0], u1 = au[mf][nf][half * 2 + 1];
                float h0 = (g0 / (1.0f + __expf(-g0))) * u0;
                float h1 = (g1 / (1.0f + __expf(-g1))) * u1;
                *(__half2*)(g_h16 + base + nf * 8) =
                    __halves2half2(__float2half_rn(h0), __float2half_rn(h1));
            }
        }
}

// out[token] += gate_wt * (h @ Wd)
__global__ void __launch_bounds__(256) k_hmma_down(float* __restrict__ out) {
    int e   = blockIdx.z;
    int cnt = g_count[e];
    int r0  = blockIdx.y * 128;
    if (r0 >= cnt) return;
    int n0  = blockIdx.x * 64;

    __shared__ __half sA[128 * SA];
    __shared__ __half sBh[32 * SB];

    int tid = threadIdx.x, lane = tid & 31, wid = tid >> 5;
    int wm = wid >> 1, wn = wid & 1;

    int arow = tid >> 1, ahalf = tid & 1;
    int slotA = r0 + arow;
    int asafe = (slotA < cnt) ? slotA : 0;
    size_t hrow = ((size_t)e * CAP + asafe) * D_FF + ahalf * 16;
    const __half* pA = g_h16 + hrow;
    __half* dA = sA + arow * SA + ahalf * 16;

    int brow = tid >> 3, bq = tid & 7;
    const __half* pB = g_wd16 + (size_t)e * D_FF * D_MODEL + (size_t)brow * D_MODEL + n0 + bq * 8;
    uint4* dBh = (uint4*)(sBh + brow * SB + bq * 8);

    uint32_t bA  = smem_u32(sA);
    uint32_t bBh = smem_u32(sBh);

    float ac[2][4][4];
#pragma unroll
    for (int i = 0; i < 2; i++)
#pragma unroll
        for (int j = 0; j < 4; j++)
#pragma unroll
            for (int q = 0; q < 4; q++) ac[i][j][q] = 0.0f;

    for (int c = 0; c < D_FF / 32; c++) {         // 64 chunks
        int k0 = c * 32;
        if (c > 0) __syncthreads();
        *(uint4*)dA       = *(const uint4*)(pA + k0);
        *(uint4*)(dA + 8) = *(const uint4*)(pA + k0 + 8);
        *dBh = *(const uint4*)(pB + (size_t)k0 * D_MODEL);
        __syncthreads();

#pragma unroll
        for (int kk = 0; kk < 32; kk += 16) {
            uint32_t ah[2][4];
#pragma unroll
            for (int mf = 0; mf < 2; mf++) {
                uint32_t ro = wm * 32 + mf * 16 + (lane & 15);
                uint32_t co = kk + (lane >> 4) * 8;
                ldsm4(ah[mf], bA + (ro * SA + co) * 2);
            }
            uint32_t kr = kk + (lane & 7) + ((lane >> 4) & 1) * 8;
            uint32_t ncol = wn * 32 + ((lane >> 3) & 1) * 8;
            uint32_t bh[4][2], r4[4];
#pragma unroll
            for (int p = 0; p < 2; p++) {
                uint32_t off = (kr * SB + ncol + p * 16) * 2;
                ldsm4t(r4, bBh + off);
                bh[p*2][0] = r4[0]; bh[p*2+1][0] = r4[1]; bh[p*2][1] = r4[2]; bh[p*2+1][1] = r4[3];
            }
#pragma unroll
            for (int mf = 0; mf < 2; mf++)
#pragma unroll
                for (int nf = 0; nf < 4; nf++)
                    mma16816(ac[mf][nf], ah[mf], bh[nf][0], bh[nf][1]);
        }
    }

    // ---- epilogue: weighted atomic scatter-add ----
    int lr = lane >> 2, lc = (lane & 3) * 2;
#pragma unroll
    for (int mf = 0; mf < 2; mf++)
#pragma unroll
        for (int half = 0; half < 2; half++) {
            int slot = r0 + wm * 32 + mf * 16 + lr + half * 8;
            if (slot >= cnt) continue;
            int   tok = g_rows[e * CAP + slot];
            float w   = g_wts [e * CAP + slot];
            float* orow = out + (size_t)tok * D_MODEL + n0 + wn * 32 + lc;
#pragma unroll
            for (int nf = 0; nf < 4; nf++) {
                atomicAdd(&orow[nf * 8 + 0], ac[mf][nf][half * 2 + 0] * w);
                atomicAdd(&orow[nf * 8 + 1], ac[mf][nf][half * 2 + 1] * w);
            }
        }
}

// ======================= launch =======================
extern "C" void kernel_launch(void* const* d_in, const int* in_sizes, int n_in,
                              void* d_out, int out_size) {
    const float* x      = (const float*)d_in[0];   // [2,1024,768]
    const float* gate_w = (const float*)d_in[1];   // [768,8]
    const float* w_gate = (const float*)d_in[2];   // [8,768,2048]
    const float* w_up   = (const float*)d_in[3];   // [8,768,2048]
    const float* w_down = (const float*)d_in[4];   // [8,2048,768]
    float* out = (float*)d_out;

    k_reset<<<512, 256>>>(out, out_size);
    k_router<<<T_TOK / 8, 256>>>(x, gate_w);
    k_scatter<<<(T_TOK * 2 + 255) / 256, 256>>>();
    k_cvt_x<<<(T_TOK * D_MODEL / 4 + 255) / 256, 256>>>(x);

    {   // weight pre-convert fp32 -> fp16
        int n4 = NE * D_MODEL * D_FF / 4;
        int gsz = (n4 + 255) / 256;
        __half *wg16, *wu16, *wd16;
        cudaGetSymbolAddress((void**)&wg16, g_wg16);
        cudaGetSymbolAddress((void**)&wu16, g_wu16);
        cudaGetSymbolAddress((void**)&wd16, g_wd16);
        k_cvt_w<<<gsz, 256>>>(w_gate, wg16, n4);
        k_cvt_w<<<gsz, 256>>>(w_up,   wu16, n4);
        k_cvt_w<<<gsz, 256>>>(w_down, wd16, n4);
    }

    {   // fused gate/up HMMA + SiLU
        dim3 grid(D_FF / 64, CAP / 128, NE);
        k_hmma_gu<<<grid, 256>>>();
    }
    {   // down HMMA + weighted scatter-add
        dim3 grid(D_MODEL / 64, CAP / 128, NE);
        k_hmma_down<<<grid, 256>>>(out);
    }
}

// round 13
// speedup vs baseline: 1.3019x; 1.3019x over previous
#include <cuda_runtime.h>
#include <cuda_fp16.h>
#include <cstdint>
#include <math.h>

#define D_MODEL 768
#define D_FF    2048
#define NE      8
#define T_TOK   2048
#define CAP     2048

// ======================= scratch (__device__ globals) =======================
__device__ int   g_count[NE];
__device__ int   g_fill[NE];
__device__ int   g_rows[NE * CAP];
__device__ float g_wts [NE * CAP];
__device__ int   g_topi[T_TOK * 2];
__device__ float g_topw[T_TOK * 2];

__device__ __align__(16) __half g_x16[T_TOK * D_MODEL];
// h = silu(g)*u, fp16: [E][CAP][D_FF]
__device__ __align__(16) __half g_h16[(size_t)NE * CAP * D_FF];

// ======================= helpers =======================
__device__ __forceinline__ uint32_t smem_u32(const void* p) {
    uint32_t a;
    asm("{ .reg .u64 t; cvta.to.shared.u64 t, %1; cvt.u32.u64 %0, t; }" : "=r"(a) : "l"(p));
    return a;
}
__device__ __forceinline__ void ldsm4(uint32_t (&r)[4], uint32_t addr) {
    asm volatile("ldmatrix.sync.aligned.m8n8.x4.shared.b16 {%0,%1,%2,%3}, [%4];"
                 : "=r"(r[0]), "=r"(r[1]), "=r"(r[2]), "=r"(r[3]) : "r"(addr));
}
__device__ __forceinline__ void ldsm4t(uint32_t (&r)[4], uint32_t addr) {
    asm volatile("ldmatrix.sync.aligned.m8n8.x4.trans.shared.b16 {%0,%1,%2,%3}, [%4];"
                 : "=r"(r[0]), "=r"(r[1]), "=r"(r[2]), "=r"(r[3]) : "r"(addr));
}
// fp16 inputs, fp32 accumulate
__device__ __forceinline__ void mma16816(float (&d)[4], const uint32_t (&a)[4],
                                         uint32_t b0, uint32_t b1) {
    asm volatile(
        "mma.sync.aligned.m16n8k16.row.col.f32.f16.f16.f32 "
        "{%0,%1,%2,%3}, {%4,%5,%6,%7}, {%8,%9}, {%0,%1,%2,%3};"
        : "+f"(d[0]), "+f"(d[1]), "+f"(d[2]), "+f"(d[3])
        : "r"(a[0]), "r"(a[1]), "r"(a[2]), "r"(a[3]), "r"(b0), "r"(b1));
}

__device__ __forceinline__ uint32_t pack2h(__half a, __half b) {
    __half2 p = __halves2half2(a, b);
    return *reinterpret_cast<uint32_t*>(&p);
}
// 8 fp32 -> 8 fp16, packed as uint4
__device__ __forceinline__ uint4 cvt8h(const float4& f0, const float4& f1) {
    return make_uint4(
        pack2h(__float2half_rn(f0.x), __float2half_rn(f0.y)),
        pack2h(__float2half_rn(f0.z), __float2half_rn(f0.w)),
        pack2h(__float2half_rn(f1.x), __float2half_rn(f1.y)),
        pack2h(__float2half_rn(f1.z), __float2half_rn(f1.w)));
}

// ======================= small kernels =======================
__global__ void k_reset(float* __restrict__ out, int out_n) {
    int i = blockIdx.x * blockDim.x + threadIdx.x;
    if (i < NE) { g_count[i] = 0; g_fill[i] = 0; }
    for (int j = i; j < out_n; j += gridDim.x * blockDim.x) out[j] = 0.0f;
}

__global__ void k_router(const float* __restrict__ x, const float* __restrict__ gw) {
    int t = blockIdx.x * (blockDim.x >> 5) + (threadIdx.x >> 5);
    int lane = threadIdx.x & 31;
    if (t >= T_TOK) return;
    const float* xr = x + (size_t)t * D_MODEL;
    float acc[NE];
#pragma unroll
    for (int e = 0; e < NE; e++) acc[e] = 0.0f;
    for (int d = lane; d < D_MODEL; d += 32) {
        float xv = xr[d];
        const float* g = gw + (size_t)d * NE;
#pragma unroll
        for (int e = 0; e < NE; e++) acc[e] += xv * g[e];
    }
#pragma unroll
    for (int off = 16; off > 0; off >>= 1)
#pragma unroll
        for (int e = 0; e < NE; e++) acc[e] += __shfl_xor_sync(0xFFFFFFFFu, acc[e], off);

    if (lane == 0) {
        int i0 = 0;
#pragma unroll
        for (int e = 1; e < NE; e++) if (acc[e] > acc[i0]) i0 = e;
        int i1 = -1; float b = -1e30f;
#pragma unroll
        for (int e = 0; e < NE; e++) if (e != i0 && acc[e] > b) { b = acc[e]; i1 = e; }
        float w1 = expf(acc[i1] - acc[i0]);
        float s  = 1.0f + w1;
        g_topi[t * 2 + 0] = i0;  g_topw[t * 2 + 0] = 1.0f / s;
        g_topi[t * 2 + 1] = i1;  g_topw[t * 2 + 1] = w1 / s;
        atomicAdd(&g_count[i0], 1);
        atomicAdd(&g_count[i1], 1);
    }
}

__global__ void k_scatter() {
    int idx = blockIdx.x * blockDim.x + threadIdx.x;
    if (idx >= T_TOK * 2) return;
    int e = g_topi[idx];
    int p = atomicAdd(&g_fill[e], 1);
    g_rows[e * CAP + p] = idx >> 1;
    g_wts [e * CAP + p] = g_topw[idx];
}

// vectorized: 4 fp32 -> 4 fp16 per thread
__global__ void k_cvt_x(const float* __restrict__ x) {
    int i = blockIdx.x * blockDim.x + threadIdx.x;
    if (i >= T_TOK * D_MODEL / 4) return;
    float4 f = reinterpret_cast<const float4*>(x)[i];
    reinterpret_cast<uint2*>(g_x16)[i] = make_uint2(
        pack2h(__float2half_rn(f.x), __float2half_rn(f.y)),
        pack2h(__float2half_rn(f.z), __float2half_rn(f.w)));
}

// ======================= HMMA GEMM kernels =======================
// Tile: M=128 x N=128, K-chunk 32. 512 threads = 16 warps in 4(m) x 4(n).
// A smem row stride 40 fp16 (80B), B 136 fp16 (272B): odd x 16B -> ldmatrix conflict-free.
#define SA 40
#define SB 136

// h = silu(x@Wg) * (x@Wu)  (weights read fp32 [k][n] native layout, converted inline)
__global__ void __launch_bounds__(512) k_hmma_gu(
    const float* __restrict__ wg, const float* __restrict__ wu)
{
    int e   = blockIdx.z;
    int cnt = g_count[e];
    int r0  = blockIdx.y * 128;
    if (r0 >= cnt) return;
    int n0  = blockIdx.x * 128;

    __shared__ __half sA[128 * SA];
    __shared__ __half sGh[32 * SB];
    __shared__ __half sUh[32 * SB];

    int tid = threadIdx.x, lane = tid & 31, wid = tid >> 5;
    int wm = wid >> 2, wn = wid & 3;

    // --- A loader: 4 threads/row, 8 cols each ---
    int arow = tid >> 2, aq = tid & 3;
    int slotA = r0 + arow;
    int tok = (slotA < cnt) ? g_rows[e * CAP + slotA] : 0;
    const __half* pA = g_x16 + (size_t)tok * D_MODEL + aq * 8;
    __half* dA = sA + arow * SA + aq * 8;

    // --- B loader: 16 threads/row, 8 cols each, 32 k-rows ---
    int brow = tid >> 4, bq = tid & 15;
    const float* pG = wg + (size_t)e * D_MODEL * D_FF + (size_t)brow * D_FF + n0 + bq * 8;
    const float* pU = wu + (size_t)e * D_MODEL * D_FF + (size_t)brow * D_FF + n0 + bq * 8;
    uint4* dGh = (uint4*)(sGh + brow * SB + bq * 8);
    uint4* dUh = (uint4*)(sUh + brow * SB + bq * 8);

    uint32_t bA  = smem_u32(sA);
    uint32_t bGh = smem_u32(sGh);
    uint32_t bUh = smem_u32(sUh);

    float ag[2][4][4], au[2][4][4];
#pragma unroll
    for (int i = 0; i < 2; i++)
#pragma unroll
        for (int j = 0; j < 4; j++)
#pragma unroll
            for (int q = 0; q < 4; q++) { ag[i][j][q] = 0.0f; au[i][j][q] = 0.0f; }

    for (int c = 0; c < D_MODEL / 32; c++) {      // 24 chunks
        int k0 = c * 32;
        if (c > 0) __syncthreads();
        // A fill: 8 fp16 per thread
        *(uint4*)dA = *(const uint4*)(pA + k0);
        // B fill: 8 fp32 -> fp16 per matrix
        {
            const float* s = pG + (size_t)k0 * D_FF;
            float4 f0 = *(const float4*)s, f1 = *(const float4*)(s + 4);
            *dGh = cvt8h(f0, f1);
        }
        {
            const float* s = pU + (size_t)k0 * D_FF;
            float4 f0 = *(const float4*)s, f1 = *(const float4*)(s + 4);
            *dUh = cvt8h(f0, f1);
        }
        __syncthreads();

#pragma unroll
        for (int kk = 0; kk < 32; kk += 16) {
            uint32_t ah[2][4];
#pragma unroll
            for (int mf = 0; mf < 2; mf++) {
                uint32_t ro = wm * 32 + mf * 16 + (lane & 15);
                uint32_t co = kk + (lane >> 4) * 8;
                ldsm4(ah[mf], bA + (ro * SA + co) * 2);
            }
            uint32_t kr = kk + (lane & 7) + ((lane >> 4) & 1) * 8;
            uint32_t ncol = wn * 32 + ((lane >> 3) & 1) * 8;
            // ---- gate ----
            {
                uint32_t bh[4][2], r4[4];
#pragma unroll
                for (int p = 0; p < 2; p++) {
                    uint32_t off = (kr * SB + ncol + p * 16) * 2;
                    ldsm4t(r4, bGh + off);
                    bh[p*2][0] = r4[0]; bh[p*2+1][0] = r4[1]; bh[p*2][1] = r4[2]; bh[p*2+1][1] = r4[3];
                }
#pragma unroll
                for (int mf = 0; mf < 2; mf++)
#pragma unroll
                    for (int nf = 0; nf < 4; nf++)
                        mma16816(ag[mf][nf], ah[mf], bh[nf][0], bh[nf][1]);
            }
            // ---- up ----
            {
                uint32_t bh[4][2], r4[4];
#pragma unroll
                for (int p = 0; p < 2; p++) {
                    uint32_t off = (kr * SB + ncol + p * 16) * 2;
                    ldsm4t(r4, bUh + off);
                    bh[p*2][0] = r4[0]; bh[p*2+1][0] = r4[1]; bh[p*2][1] = r4[2]; bh[p*2+1][1] = r4[3];
                }
#pragma unroll
                for (int mf = 0; mf < 2; mf++)
#pragma unroll
                    for (int nf = 0; nf < 4; nf++)
                        mma16816(au[mf][nf], ah[mf], bh[nf][0], bh[nf][1]);
            }
        }
    }

    // ---- epilogue: h = silu(g)*u -> fp16 ----
    int lr = lane >> 2, lc = (lane & 3) * 2;
#pragma unroll
    for (int mf = 0; mf < 2; mf++)
#pragma unroll
        for (int half = 0; half < 2; half++) {
            int slot = r0 + wm * 32 + mf * 16 + lr + half * 8;
            if (slot >= cnt) continue;
            size_t base = ((size_t)e * CAP + slot) * D_FF + n0 + wn * 32 + lc;
#pragma unroll
            for (int nf = 0; nf < 4; nf++) {
                float g0 = ag[mf][nf][half * 2 + 0], g1 = ag[mf][nf][half * 2 + 1];
                float u0 = au[mf][nf][half * 2 + 0], u1 = au[mf][nf][half * 2 + 1];
                float h0 = (g0 / (1.0f + __expf(-g0))) * u0;
                float h1 = (g1 / (1.0f + __expf(-g1))) * u1;
                *(__half2*)(g_h16 + base + nf * 8) =
                    __halves2half2(__float2half_rn(h0), __float2half_rn(h1));
            }
        }
}

// out[token] += gate_wt * (h @ Wd)
__global__ void __launch_bounds__(512) k_hmma_down(
    const float* __restrict__ wd, float* __restrict__ out)
{
    int e   = blockIdx.z;
    int cnt = g_count[e];
    int r0  = blockIdx.y * 128;
    if (r0 >= cnt) return;
    int n0  = blockIdx.x * 128;

    __shared__ __half sA[128 * SA];
    __shared__ __half sBh[32 * SB];

    int tid = threadIdx.x, lane = tid & 31, wid = tid >> 5;
    int wm = wid >> 2, wn = wid & 3;

    int arow = tid >> 2, aq = tid & 3;
    int slotA = r0 + arow;
    int asafe = (slotA < cnt) ? slotA : 0;
    size_t hrow = ((size_t)e * CAP + asafe) * D_FF + aq * 8;
    const __half* pA = g_h16 + hrow;
    __half* dA = sA + arow * SA + aq * 8;

    int brow = tid >> 4, bq = tid & 15;
    const float* pB = wd + (size_t)e * D_FF * D_MODEL + (size_t)brow * D_MODEL + n0 + bq * 8;
    uint4* dBh = (uint4*)(sBh + brow * SB + bq * 8);

    uint32_t bA  = smem_u32(sA);
    uint32_t bBh = smem_u32(sBh);

    float ac[2][4][4];
#pragma unroll
    for (int i = 0; i < 2; i++)
#pragma unroll
        for (int j = 0; j < 4; j++)
#pragma unroll
            for (int q = 0; q < 4; q++) ac[i][j][q] = 0.0f;

    for (int c = 0; c < D_FF / 32; c++) {         // 64 chunks
        int k0 = c * 32;
        if (c > 0) __syncthreads();
        *(uint4*)dA = *(const uint4*)(pA + k0);
        {
            const float* s = pB + (size_t)k0 * D_MODEL;
            float4 f0 = *(const float4*)s, f1 = *(const float4*)(s + 4);
            *dBh = cvt8h(f0, f1);
        }
        __syncthreads();

#pragma unroll
        for (int kk = 0; kk < 32; kk += 16) {
            uint32_t ah[2][4];
#pragma unroll
            for (int mf = 0; mf < 2; mf++) {
                uint32_t ro = wm * 32 + mf * 16 + (lane & 15);
                uint32_t co = kk + (lane >> 4) * 8;
                ldsm4(ah[mf], bA + (ro * SA + co) * 2);
            }
            uint32_t kr = kk + (lane & 7) + ((lane >> 4) & 1) * 8;
            uint32_t ncol = wn * 32 + ((lane >> 3) & 1) * 8;
            uint32_t bh[4][2], r4[4];
#pragma unroll
            for (int p = 0; p < 2; p++) {
                uint32_t off = (kr * SB + ncol + p * 16) * 2;
                ldsm4t(r4, bBh + off);
                bh[p*2][0] = r4[0]; bh[p*2+1][0] = r4[1]; bh[p*2][1] = r4[2]; bh[p*2+1][1] = r4[3];
            }
#pragma unroll
            for (int mf = 0; mf < 2; mf++)
#pragma unroll
                for (int nf = 0; nf < 4; nf++)
                    mma16816(ac[mf][nf], ah[mf], bh[nf][0], bh[nf][1]);
        }
    }

    // ---- epilogue: weighted atomic scatter-add ----
    int lr = lane >> 2, lc = (lane & 3) * 2;
#pragma unroll
    for (int mf = 0; mf < 2; mf++)
#pragma unroll
        for (int half = 0; half < 2; half++) {
            int slot = r0 + wm * 32 + mf * 16 + lr + half * 8;
            if (slot >= cnt) continue;
            int   tok = g_rows[e * CAP + slot];
            float w   = g_wts [e * CAP + slot];
            float* orow = out + (size_t)tok * D_MODEL + n0 + wn * 32 + lc;
#pragma unroll
            for (int nf = 0; nf < 4; nf++) {
                atomicAdd(&orow[nf * 8 + 0], ac[mf][nf][half * 2 + 0] * w);
                atomicAdd(&orow[nf * 8 + 1], ac[mf][nf][half * 2 + 1] * w);
            }
        }
}

// ======================= launch =======================
extern "C" void kernel_launch(void* const* d_in, const int* in_sizes, int n_in,
                              void* d_out, int out_size) {
    const float* x      = (const float*)d_in[0];   // [2,1024,768]
    const float* gate_w = (const float*)d_in[1];   // [768,8]
    const float* w_gate = (const float*)d_in[2];   // [8,768,2048]
    const float* w_up   = (const float*)d_in[3];   // [8,768,2048]
    const float* w_down = (const float*)d_in[4];   // [8,2048,768]
    float* out = (float*)d_out;

    k_reset<<<512, 256>>>(out, out_size);
    k_router<<<T_TOK / 8, 256>>>(x, gate_w);
    k_scatter<<<(T_TOK * 2 + 255) / 256, 256>>>();
    k_cvt_x<<<(T_TOK * D_MODEL / 4 + 255) / 256, 256>>>(x);

    {   // fused gate/up HMMA + SiLU
        dim3 grid(D_FF / 128, CAP / 128, NE);
        k_hmma_gu<<<grid, 512>>>(w_gate, w_up);
    }
    {   // down HMMA + weighted scatter-add
        dim3 grid(D_MODEL / 128, CAP / 128, NE);
        k_hmma_down<<<grid, 512>>>(w_down, out);
    }
}

// round 14
// speedup vs baseline: 1.5013x; 1.1531x over previous
#include <cuda_runtime.h>
#include <cuda_fp16.h>
#include <cstdint>
#include <math.h>

#define D_MODEL 768
#define D_FF    2048
#define NE      8
#define T_TOK   2048
#define CAP     2048

// ======================= scratch (__device__ globals) =======================
__device__ int   g_count[NE];
__device__ int   g_fill[NE];
__device__ int   g_rows[NE * CAP];
__device__ float g_wts [NE * CAP];
__device__ int   g_topi[T_TOK * 2];
__device__ float g_topw[T_TOK * 2];

__device__ __align__(16) __half g_x16[T_TOK * D_MODEL];
// h = silu(g)*u, fp16: [E][CAP][D_FF]
__device__ __align__(16) __half g_h16[(size_t)NE * CAP * D_FF];

// ======================= helpers =======================
__device__ __forceinline__ uint32_t smem_u32(const void* p) {
    uint32_t a;
    asm("{ .reg .u64 t; cvta.to.shared.u64 t, %1; cvt.u32.u64 %0, t; }" : "=r"(a) : "l"(p));
    return a;
}
__device__ __forceinline__ void ldsm4(uint32_t (&r)[4], uint32_t addr) {
    asm volatile("ldmatrix.sync.aligned.m8n8.x4.shared.b16 {%0,%1,%2,%3}, [%4];"
                 : "=r"(r[0]), "=r"(r[1]), "=r"(r[2]), "=r"(r[3]) : "r"(addr));
}
__device__ __forceinline__ void ldsm4t(uint32_t (&r)[4], uint32_t addr) {
    asm volatile("ldmatrix.sync.aligned.m8n8.x4.trans.shared.b16 {%0,%1,%2,%3}, [%4];"
                 : "=r"(r[0]), "=r"(r[1]), "=r"(r[2]), "=r"(r[3]) : "r"(addr));
}
// fp16 inputs, fp32 accumulate
__device__ __forceinline__ void mma16816(float (&d)[4], const uint32_t (&a)[4],
                                         uint32_t b0, uint32_t b1) {
    asm volatile(
        "mma.sync.aligned.m16n8k16.row.col.f32.f16.f16.f32 "
        "{%0,%1,%2,%3}, {%4,%5,%6,%7}, {%8,%9}, {%0,%1,%2,%3};"
        : "+f"(d[0]), "+f"(d[1]), "+f"(d[2]), "+f"(d[3])
        : "r"(a[0]), "r"(a[1]), "r"(a[2]), "r"(a[3]), "r"(b0), "r"(b1));
}

__device__ __forceinline__ uint32_t pack2h(__half a, __half b) {
    __half2 p = __halves2half2(a, b);
    return *reinterpret_cast<uint32_t*>(&p);
}
// 8 fp32 -> 8 fp16, packed as uint4
__device__ __forceinline__ uint4 cvt8h(const float4& f0, const float4& f1) {
    return make_uint4(
        pack2h(__float2half_rn(f0.x), __float2half_rn(f0.y)),
        pack2h(__float2half_rn(f0.z), __float2half_rn(f0.w)),
        pack2h(__float2half_rn(f1.x), __float2half_rn(f1.y)),
        pack2h(__float2half_rn(f1.z), __float2half_rn(f1.w)));
}

// ======================= small kernels =======================
__global__ void k_reset(float* __restrict__ out, int out_n) {
    int i = blockIdx.x * blockDim.x + threadIdx.x;
    if (i < NE) { g_count[i] = 0; g_fill[i] = 0; }
    for (int j = i; j < out_n; j += gridDim.x * blockDim.x) out[j] = 0.0f;
}

__global__ void k_router(const float* __restrict__ x, const float* __restrict__ gw) {
    int t = blockIdx.x * (blockDim.x >> 5) + (threadIdx.x >> 5);
    int lane = threadIdx.x & 31;
    if (t >= T_TOK) return;
    const float* xr = x + (size_t)t * D_MODEL;
    float acc[NE];
#pragma unroll
    for (int e = 0; e < NE; e++) acc[e] = 0.0f;
    for (int d = lane; d < D_MODEL; d += 32) {
        float xv = xr[d];
        const float* g = gw + (size_t)d * NE;
#pragma unroll
        for (int e = 0; e < NE; e++) acc[e] += xv * g[e];
    }
#pragma unroll
    for (int off = 16; off > 0; off >>= 1)
#pragma unroll
        for (int e = 0; e < NE; e++) acc[e] += __shfl_xor_sync(0xFFFFFFFFu, acc[e], off);

    if (lane == 0) {
        int i0 = 0;
#pragma unroll
        for (int e = 1; e < NE; e++) if (acc[e] > acc[i0]) i0 = e;
        int i1 = -1; float b = -1e30f;
#pragma unroll
        for (int e = 0; e < NE; e++) if (e != i0 && acc[e] > b) { b = acc[e]; i1 = e; }
        float w1 = expf(acc[i1] - acc[i0]);
        float s  = 1.0f + w1;
        g_topi[t * 2 + 0] = i0;  g_topw[t * 2 + 0] = 1.0f / s;
        g_topi[t * 2 + 1] = i1;  g_topw[t * 2 + 1] = w1 / s;
        atomicAdd(&g_count[i0], 1);
        atomicAdd(&g_count[i1], 1);
    }
}

__global__ void k_scatter() {
    int idx = blockIdx.x * blockDim.x + threadIdx.x;
    if (idx >= T_TOK * 2) return;
    int e = g_topi[idx];
    int p = atomicAdd(&g_fill[e], 1);
    g_rows[e * CAP + p] = idx >> 1;
    g_wts [e * CAP + p] = g_topw[idx];
}

// vectorized: 4 fp32 -> 4 fp16 per thread
__global__ void k_cvt_x(const float* __restrict__ x) {
    int i = blockIdx.x * blockDim.x + threadIdx.x;
    if (i >= T_TOK * D_MODEL / 4) return;
    float4 f = reinterpret_cast<const float4*>(x)[i];
    reinterpret_cast<uint2*>(g_x16)[i] = make_uint2(
        pack2h(__float2half_rn(f.x), __float2half_rn(f.y)),
        pack2h(__float2half_rn(f.z), __float2half_rn(f.w)));
}

// ======================= HMMA GEMM kernels =======================
// A smem row stride 40 fp16 (80B); B strides 72 (gu) / 136 (down) fp16 -> conflict-free.
#define SA  40
#define SB  72
#define SBD 136

// gu: tile M=128 x N=64, K-chunk 32, 256 thr = 8 warps 4(m) x 2(n). (round-10 champion, unchanged)
__global__ void __launch_bounds__(256) k_hmma_gu(
    const float* __restrict__ wg, const float* __restrict__ wu)
{
    int e   = blockIdx.z;
    int cnt = g_count[e];
    int r0  = blockIdx.y * 128;
    if (r0 >= cnt) return;
    int n0  = blockIdx.x * 64;

    __shared__ __half sA[128 * SA];
    __shared__ __half sGh[32 * SB];
    __shared__ __half sUh[32 * SB];

    int tid = threadIdx.x, lane = tid & 31, wid = tid >> 5;
    int wm = wid >> 1, wn = wid & 1;

    int arow = tid >> 1, ahalf = tid & 1;
    int slotA = r0 + arow;
    int tok = (slotA < cnt) ? g_rows[e * CAP + slotA] : 0;
    const __half* pA = g_x16 + (size_t)tok * D_MODEL + ahalf * 16;
    __half* dA = sA + arow * SA + ahalf * 16;

    int brow = tid >> 3, bq = tid & 7;
    const float* pG = wg + (size_t)e * D_MODEL * D_FF + (size_t)brow * D_FF + n0 + bq * 8;
    const float* pU = wu + (size_t)e * D_MODEL * D_FF + (size_t)brow * D_FF + n0 + bq * 8;
    uint4* dGh = (uint4*)(sGh + brow * SB + bq * 8);
    uint4* dUh = (uint4*)(sUh + brow * SB + bq * 8);

    uint32_t bA  = smem_u32(sA);
    uint32_t bGh = smem_u32(sGh);
    uint32_t bUh = smem_u32(sUh);

    float ag[2][4][4], au[2][4][4];
#pragma unroll
    for (int i = 0; i < 2; i++)
#pragma unroll
        for (int j = 0; j < 4; j++)
#pragma unroll
            for (int q = 0; q < 4; q++) { ag[i][j][q] = 0.0f; au[i][j][q] = 0.0f; }

    for (int c = 0; c < D_MODEL / 32; c++) {      // 24 chunks
        int k0 = c * 32;
        if (c > 0) __syncthreads();
        *(uint4*)dA       = *(const uint4*)(pA + k0);
        *(uint4*)(dA + 8) = *(const uint4*)(pA + k0 + 8);
        {
            const float* s = pG + (size_t)k0 * D_FF;
            float4 f0 = *(const float4*)s, f1 = *(const float4*)(s + 4);
            *dGh = cvt8h(f0, f1);
        }
        {
            const float* s = pU + (size_t)k0 * D_FF;
            float4 f0 = *(const float4*)s, f1 = *(const float4*)(s + 4);
            *dUh = cvt8h(f0, f1);
        }
        __syncthreads();

#pragma unroll
        for (int kk = 0; kk < 32; kk += 16) {
            uint32_t ah[2][4];
#pragma unroll
            for (int mf = 0; mf < 2; mf++) {
                uint32_t ro = wm * 32 + mf * 16 + (lane & 15);
                uint32_t co = kk + (lane >> 4) * 8;
                ldsm4(ah[mf], bA + (ro * SA + co) * 2);
            }
            uint32_t kr = kk + (lane & 7) + ((lane >> 4) & 1) * 8;
            uint32_t ncol = wn * 32 + ((lane >> 3) & 1) * 8;
            {
                uint32_t bh[4][2], r4[4];
#pragma unroll
                for (int p = 0; p < 2; p++) {
                    uint32_t off = (kr * SB + ncol + p * 16) * 2;
                    ldsm4t(r4, bGh + off);
                    bh[p*2][0] = r4[0]; bh[p*2+1][0] = r4[1]; bh[p*2][1] = r4[2]; bh[p*2+1][1] = r4[3];
                }
#pragma unroll
                for (int mf = 0; mf < 2; mf++)
#pragma unroll
                    for (int nf = 0; nf < 4; nf++)
                        mma16816(ag[mf][nf], ah[mf], bh[nf][0], bh[nf][1]);
            }
            {
                uint32_t bh[4][2], r4[4];
#pragma unroll
                for (int p = 0; p < 2; p++) {
                    uint32_t off = (kr * SB + ncol + p * 16) * 2;
                    ldsm4t(r4, bUh + off);
                    bh[p*2][0] = r4[0]; bh[p*2+1][0] = r4[1]; bh[p*2][1] = r4[2]; bh[p*2+1][1] = r4[3];
                }
#pragma unroll
                for (int mf = 0; mf < 2; mf++)
#pragma unroll
                    for (int nf = 0; nf < 4; nf++)
                        mma16816(au[mf][nf], ah[mf], bh[nf][0], bh[nf][1]);
            }
        }
    }

    int lr = lane >> 2, lc = (lane & 3) * 2;
#pragma unroll
    for (int mf = 0; mf < 2; mf++)
#pragma unroll
        for (int half = 0; half < 2; half++) {
            int slot = r0 + wm * 32 + mf * 16 + lr + half * 8;
            if (slot >= cnt) continue;
            size_t base = ((size_t)e * CAP + slot) * D_FF + n0 + wn * 32 + lc;
#pragma unroll
            for (int nf = 0; nf < 4; nf++) {
                float g0 = ag[mf][nf][half * 2 + 0], g1 = ag[mf][nf][half * 2 + 1];
                float u0 = au[mf][nf][half * 2 + 0], u1 = au[mf][nf][half * 2 + 1];
                float h0 = (g0 / (1.0f + __expf(-g0))) * u0;
                float h1 = (g1 / (1.0f + __expf(-g1))) * u1;
                *(__half2*)(g_h16 + base + nf * 8) =
                    __halves2half2(__float2half_rn(h0), __float2half_rn(h1));
            }
        }
}

// down: tile M=128 x N=128, K-chunk 32, 256 thr = 8 warps 4(m) x 2(n), warp tile 32x64 (nf=8).
__global__ void __launch_bounds__(256) k_hmma_down(
    const float* __restrict__ wd, float* __restrict__ out)
{
    int e   = blockIdx.z;
    int cnt = g_count[e];
    int r0  = blockIdx.y * 128;
    if (r0 >= cnt) return;
    int n0  = blockIdx.x * 128;

    __shared__ __half sA[128 * SA];
    __shared__ __half sBh[32 * SBD];

    int tid = threadIdx.x, lane = tid & 31, wid = tid >> 5;
    int wm = wid >> 1, wn = wid & 1;

    int arow = tid >> 1, ahalf = tid & 1;
    int slotA = r0 + arow;
    int asafe = (slotA < cnt) ? slotA : 0;
    size_t hrow = ((size_t)e * CAP + asafe) * D_FF + ahalf * 16;
    const __half* pA = g_h16 + hrow;
    __half* dA = sA + arow * SA + ahalf * 16;

    // B loader: 32 k-rows x 128 cols; 8 threads/row, 16 fp32 -> 16 fp16 each
    int brow = tid >> 3, bq = tid & 7;
    const float* pB = wd + (size_t)e * D_FF * D_MODEL + (size_t)brow * D_MODEL + n0 + bq * 16;
    __half* dBh = sBh + brow * SBD + bq * 16;

    uint32_t bA  = smem_u32(sA);
    uint32_t bBh = smem_u32(sBh);

    float ac[2][8][4];
#pragma unroll
    for (int i = 0; i < 2; i++)
#pragma unroll
        for (int j = 0; j < 8; j++)
#pragma unroll
            for (int q = 0; q < 4; q++) ac[i][j][q] = 0.0f;

    for (int c = 0; c < D_FF / 32; c++) {         // 64 chunks
        int k0 = c * 32;
        if (c > 0) __syncthreads();
        *(uint4*)dA       = *(const uint4*)(pA + k0);
        *(uint4*)(dA + 8) = *(const uint4*)(pA + k0 + 8);
        {
            const float* s = pB + (size_t)k0 * D_MODEL;
            float4 f0 = *(const float4*)s,       f1 = *(const float4*)(s + 4);
            float4 f2 = *(const float4*)(s + 8), f3 = *(const float4*)(s + 12);
            *(uint4*)dBh       = cvt8h(f0, f1);
            *(uint4*)(dBh + 8) = cvt8h(f2, f3);
        }
        __syncthreads();

#pragma unroll
        for (int kk = 0; kk < 32; kk += 16) {
            uint32_t ah[2][4];
#pragma unroll
            for (int mf = 0; mf < 2; mf++) {
                uint32_t ro = wm * 32 + mf * 16 + (lane & 15);
                uint32_t co = kk + (lane >> 4) * 8;
                ldsm4(ah[mf], bA + (ro * SA + co) * 2);
            }
            uint32_t kr = kk + (lane & 7) + ((lane >> 4) & 1) * 8;
            uint32_t ncol = wn * 64 + ((lane >> 3) & 1) * 8;
            uint32_t bh[8][2], r4[4];
#pragma unroll
            for (int p = 0; p < 4; p++) {
                uint32_t off = (kr * SBD + ncol + p * 16) * 2;
                ldsm4t(r4, bBh + off);
                bh[p*2][0] = r4[0]; bh[p*2+1][0] = r4[1]; bh[p*2][1] = r4[2]; bh[p*2+1][1] = r4[3];
            }
#pragma unroll
            for (int mf = 0; mf < 2; mf++)
#pragma unroll
                for (int nf = 0; nf < 8; nf++)
                    mma16816(ac[mf][nf], ah[mf], bh[nf][0], bh[nf][1]);
        }
    }

    // ---- epilogue: weighted atomic scatter-add ----
    int lr = lane >> 2, lc = (lane & 3) * 2;
#pragma unroll
    for (int mf = 0; mf < 2; mf++)
#pragma unroll
        for (int half = 0; half < 2; half++) {
            int slot = r0 + wm * 32 + mf * 16 + lr + half * 8;
            if (slot >= cnt) continue;
            int   tok = g_rows[e * CAP + slot];
            float w   = g_wts [e * CAP + slot];
            float* orow = out + (size_t)tok * D_MODEL + n0 + wn * 64 + lc;
#pragma unroll
            for (int nf = 0; nf < 8; nf++) {
                atomicAdd(&orow[nf * 8 + 0], ac[mf][nf][half * 2 + 0] * w);
                atomicAdd(&orow[nf * 8 + 1], ac[mf][nf][half * 2 + 1] * w);
            }
        }
}

// ======================= launch =======================
extern "C" void kernel_launch(void* const* d_in, const int* in_sizes, int n_in,
                              void* d_out, int out_size) {
    const float* x      = (const float*)d_in[0];   // [2,1024,768]
    const float* gate_w = (const float*)d_in[1];   // [768,8]
    const float* w_gate = (const float*)d_in[2];   // [8,768,2048]
    const float* w_up   = (const float*)d_in[3];   // [8,768,2048]
    const float* w_down = (const float*)d_in[4];   // [8,2048,768]
    float* out = (float*)d_out;

    k_reset<<<512, 256>>>(out, out_size);
    k_router<<<T_TOK / 8, 256>>>(x, gate_w);
    k_scatter<<<(T_TOK * 2 + 255) / 256, 256>>>();
    k_cvt_x<<<(T_TOK * D_MODEL / 4 + 255) / 256, 256>>>(x);

    {   // fused gate/up HMMA + SiLU
        dim3 grid(D_FF / 64, CAP / 128, NE);
        k_hmma_gu<<<grid, 256>>>(w_gate, w_up);
    }
    {   // down HMMA + weighted scatter-add (N-tile 128)
        dim3 grid(D_MODEL / 128, CAP / 128, NE);
        k_hmma_down<<<grid, 256>>>(w_down, out);
    }
}

// round 15
// speedup vs baseline: 1.7013x; 1.1333x over previous
#include <cuda_runtime.h>
#include <cuda_fp16.h>
#include <cstdint>
#include <math.h>

#define D_MODEL 768
#define D_FF    2048
#define NE      8
#define T_TOK   2048
#define CAP     2048

// ======================= scratch (__device__ globals) =======================
__device__ int   g_fill[NE];                 // per-expert row count (filled by k_front)
__device__ int   g_rows[NE * CAP];
__device__ float g_wts [NE * CAP];

__device__ __align__(16) __half g_x16[T_TOK * D_MODEL];
// h = silu(g)*u, fp16: [E][CAP][D_FF]
__device__ __align__(16) __half g_h16[(size_t)NE * CAP * D_FF];

// ======================= helpers =======================
__device__ __forceinline__ uint32_t smem_u32(const void* p) {
    uint32_t a;
    asm("{ .reg .u64 t; cvta.to.shared.u64 t, %1; cvt.u32.u64 %0, t; }" : "=r"(a) : "l"(p));
    return a;
}
__device__ __forceinline__ void ldsm4(uint32_t (&r)[4], uint32_t addr) {
    asm volatile("ldmatrix.sync.aligned.m8n8.x4.shared.b16 {%0,%1,%2,%3}, [%4];"
                 : "=r"(r[0]), "=r"(r[1]), "=r"(r[2]), "=r"(r[3]) : "r"(addr));
}
__device__ __forceinline__ void ldsm4t(uint32_t (&r)[4], uint32_t addr) {
    asm volatile("ldmatrix.sync.aligned.m8n8.x4.trans.shared.b16 {%0,%1,%2,%3}, [%4];"
                 : "=r"(r[0]), "=r"(r[1]), "=r"(r[2]), "=r"(r[3]) : "r"(addr));
}
// fp16 inputs, fp32 accumulate
__device__ __forceinline__ void mma16816(float (&d)[4], const uint32_t (&a)[4],
                                         uint32_t b0, uint32_t b1) {
    asm volatile(
        "mma.sync.aligned.m16n8k16.row.col.f32.f16.f16.f32 "
        "{%0,%1,%2,%3}, {%4,%5,%6,%7}, {%8,%9}, {%0,%1,%2,%3};"
        : "+f"(d[0]), "+f"(d[1]), "+f"(d[2]), "+f"(d[3])
        : "r"(a[0]), "r"(a[1]), "r"(a[2]), "r"(a[3]), "r"(b0), "r"(b1));
}

__device__ __forceinline__ uint32_t pack2h(__half a, __half b) {
    __half2 p = __halves2half2(a, b);
    return *reinterpret_cast<uint32_t*>(&p);
}
// 8 fp32 -> 8 fp16, packed as uint4
__device__ __forceinline__ uint4 cvt8h(const float4& f0, const float4& f1) {
    return make_uint4(
        pack2h(__float2half_rn(f0.x), __float2half_rn(f0.y)),
        pack2h(__float2half_rn(f0.z), __float2half_rn(f0.w)),
        pack2h(__float2half_rn(f1.x), __float2half_rn(f1.y)),
        pack2h(__float2half_rn(f1.z), __float2half_rn(f1.w)));
}

// ======================= small kernels =======================
// zero output (vectorized) + per-expert counters
__global__ void k_reset(float* __restrict__ out, int out_n) {
    int i = blockIdx.x * blockDim.x + threadIdx.x;
    if (i < NE) g_fill[i] = 0;
    int n4 = out_n >> 2;
    float4 z4 = make_float4(0.f, 0.f, 0.f, 0.f);
    for (int j = i; j < n4; j += gridDim.x * blockDim.x)
        reinterpret_cast<float4*>(out)[j] = z4;
    // tail
    for (int j = n4 * 4 + i; j < out_n; j += gridDim.x * blockDim.x)
        out[j] = 0.0f;
}

// fused: router (softmax top-2) + scatter + x fp32->fp16 conversion. One warp/token.
__global__ void k_front(const float* __restrict__ x, const float* __restrict__ gw) {
    int t = blockIdx.x * (blockDim.x >> 5) + (threadIdx.x >> 5);
    int lane = threadIdx.x & 31;
    if (t >= T_TOK) return;
    const float* xr = x + (size_t)t * D_MODEL;
    __half*      xo = g_x16 + (size_t)t * D_MODEL;

    float acc[NE];
#pragma unroll
    for (int e = 0; e < NE; e++) acc[e] = 0.0f;
    for (int d = lane; d < D_MODEL; d += 32) {
        float xv = xr[d];
        xo[d] = __float2half_rn(xv);          // fused conversion (x already in regs)
        const float* g = gw + (size_t)d * NE;
#pragma unroll
        for (int e = 0; e < NE; e++) acc[e] += xv * g[e];
    }
#pragma unroll
    for (int off = 16; off > 0; off >>= 1)
#pragma unroll
        for (int e = 0; e < NE; e++) acc[e] += __shfl_xor_sync(0xFFFFFFFFu, acc[e], off);

    if (lane == 0) {
        int i0 = 0;
#pragma unroll
        for (int e = 1; e < NE; e++) if (acc[e] > acc[i0]) i0 = e;
        int i1 = -1; float b = -1e30f;
#pragma unroll
        for (int e = 0; e < NE; e++) if (e != i0 && acc[e] > b) { b = acc[e]; i1 = e; }
        float w1 = expf(acc[i1] - acc[i0]);
        float s  = 1.0f + w1;
        // fused scatter (atomic append)
        int p0 = atomicAdd(&g_fill[i0], 1);
        g_rows[i0 * CAP + p0] = t;  g_wts[i0 * CAP + p0] = 1.0f / s;
        int p1 = atomicAdd(&g_fill[i1], 1);
        g_rows[i1 * CAP + p1] = t;  g_wts[i1 * CAP + p1] = w1 / s;
    }
}

// ======================= HMMA GEMM kernels (round-10 champion, unchanged) =======================
// Tile: M=128 x N=64, K-chunk 32. 256 threads = 8 warps in 4(m) x 2(n).
// A smem row stride 40 fp16 (80B), B 72 fp16 (144B) -> ldmatrix conflict-free.
#define SA 40
#define SB 72

// h = silu(x@Wg) * (x@Wu)  (weights read fp32 [k][n] native layout, converted inline)
__global__ void __launch_bounds__(256) k_hmma_gu(
    const float* __restrict__ wg, const float* __restrict__ wu)
{
    int e   = blockIdx.z;
    int cnt = g_fill[e];
    int r0  = blockIdx.y * 128;
    if (r0 >= cnt) return;
    int n0  = blockIdx.x * 64;

    __shared__ __half sA[128 * SA];
    __shared__ __half sGh[32 * SB];
    __shared__ __half sUh[32 * SB];

    int tid = threadIdx.x, lane = tid & 31, wid = tid >> 5;
    int wm = wid >> 1, wn = wid & 1;

    int arow = tid >> 1, ahalf = tid & 1;
    int slotA = r0 + arow;
    int tok = (slotA < cnt) ? g_rows[e * CAP + slotA] : 0;
    const __half* pA = g_x16 + (size_t)tok * D_MODEL + ahalf * 16;
    __half* dA = sA + arow * SA + ahalf * 16;

    int brow = tid >> 3, bq = tid & 7;
    const float* pG = wg + (size_t)e * D_MODEL * D_FF + (size_t)brow * D_FF + n0 + bq * 8;
    const float* pU = wu + (size_t)e * D_MODEL * D_FF + (size_t)brow * D_FF + n0 + bq * 8;
    uint4* dGh = (uint4*)(sGh + brow * SB + bq * 8);
    uint4* dUh = (uint4*)(sUh + brow * SB + bq * 8);

    uint32_t bA  = smem_u32(sA);
    uint32_t bGh = smem_u32(sGh);
    uint32_t bUh = smem_u32(sUh);

    float ag[2][4][4], au[2][4][4];
#pragma unroll
    for (int i = 0; i < 2; i++)
#pragma unroll
        for (int j = 0; j < 4; j++)
#pragma unroll
            for (int q = 0; q < 4; q++) { ag[i][j][q] = 0.0f; au[i][j][q] = 0.0f; }

    for (int c = 0; c < D_MODEL / 32; c++) {      // 24 chunks
        int k0 = c * 32;
        if (c > 0) __syncthreads();
        *(uint4*)dA       = *(const uint4*)(pA + k0);
        *(uint4*)(dA + 8) = *(const uint4*)(pA + k0 + 8);
        {
            const float* s = pG + (size_t)k0 * D_FF;
            float4 f0 = *(const float4*)s, f1 = *(const float4*)(s + 4);
            *dGh = cvt8h(f0, f1);
        }
        {
            const float* s = pU + (size_t)k0 * D_FF;
            float4 f0 = *(const float4*)s, f1 = *(const float4*)(s + 4);
            *dUh = cvt8h(f0, f1);
        }
        __syncthreads();

#pragma unroll
        for (int kk = 0; kk < 32; kk += 16) {
            uint32_t ah[2][4];
#pragma unroll
            for (int mf = 0; mf < 2; mf++) {
                uint32_t ro = wm * 32 + mf * 16 + (lane & 15);
                uint32_t co = kk + (lane >> 4) * 8;
                ldsm4(ah[mf], bA + (ro * SA + co) * 2);
            }
            uint32_t kr = kk + (lane & 7) + ((lane >> 4) & 1) * 8;
            uint32_t ncol = wn * 32 + ((lane >> 3) & 1) * 8;
            {
                uint32_t bh[4][2], r4[4];
#pragma unroll
                for (int p = 0; p < 2; p++) {
                    uint32_t off = (kr * SB + ncol + p * 16) * 2;
                    ldsm4t(r4, bGh + off);
                    bh[p*2][0] = r4[0]; bh[p*2+1][0] = r4[1]; bh[p*2][1] = r4[2]; bh[p*2+1][1] = r4[3];
                }
#pragma unroll
                for (int mf = 0; mf < 2; mf++)
#pragma unroll
                    for (int nf = 0; nf < 4; nf++)
                        mma16816(ag[mf][nf], ah[mf], bh[nf][0], bh[nf][1]);
            }
            {
                uint32_t bh[4][2], r4[4];
#pragma unroll
                for (int p = 0; p < 2; p++) {
                    uint32_t off = (kr * SB + ncol + p * 16) * 2;
                    ldsm4t(r4, bUh + off);
                    bh[p*2][0] = r4[0]; bh[p*2+1][0] = r4[1]; bh[p*2][1] = r4[2]; bh[p*2+1][1] = r4[3];
                }
#pragma unroll
                for (int mf = 0; mf < 2; mf++)
#pragma unroll
                    for (int nf = 0; nf < 4; nf++)
                        mma16816(au[mf][nf], ah[mf], bh[nf][0], bh[nf][1]);
            }
        }
    }

    int lr = lane >> 2, lc = (lane & 3) * 2;
#pragma unroll
    for (int mf = 0; mf < 2; mf++)
#pragma unroll
        for (int half = 0; half < 2; half++) {
            int slot = r0 + wm * 32 + mf * 16 + lr + half * 8;
            if (slot >= cnt) continue;
            size_t base = ((size_t)e * CAP + slot) * D_FF + n0 + wn * 32 + lc;
#pragma unroll
            for (int nf = 0; nf < 4; nf++) {
                float g0 = ag[mf][nf][half * 2 + 0], g1 = ag[mf][nf][half * 2 + 1];
                float u0 = au[mf][nf][half * 2 + 0], u1 = au[mf][nf][half * 2 + 1];
                float h0 = (g0 / (1.0f + __expf(-g0))) * u0;
                float h1 = (g1 / (1.0f + __expf(-g1))) * u1;
                *(__half2*)(g_h16 + base + nf * 8) =
                    __halves2half2(__float2half_rn(h0), __float2half_rn(h1));
            }
        }
}

// out[token] += gate_wt * (h @ Wd)
__global__ void __launch_bounds__(256) k_hmma_down(
    const float* __restrict__ wd, float* __restrict__ out)
{
    int e   = blockIdx.z;
    int cnt = g_fill[e];
    int r0  = blockIdx.y * 128;
    if (r0 >= cnt) return;
    int n0  = blockIdx.x * 64;

    __shared__ __half sA[128 * SA];
    __shared__ __half sBh[32 * SB];

    int tid = threadIdx.x, lane = tid & 31, wid = tid >> 5;
    int wm = wid >> 1, wn = wid & 1;

    int arow = tid >> 1, ahalf = tid & 1;
    int slotA = r0 + arow;
    int asafe = (slotA < cnt) ? slotA : 0;
    size_t hrow = ((size_t)e * CAP + asafe) * D_FF + ahalf * 16;
    const __half* pA = g_h16 + hrow;
    __half* dA = sA + arow * SA + ahalf * 16;

    int brow = tid >> 3, bq = tid & 7;
    const float* pB = wd + (size_t)e * D_FF * D_MODEL + (size_t)brow * D_MODEL + n0 + bq * 8;
    uint4* dBh = (uint4*)(sBh + brow * SB + bq * 8);

    uint32_t bA  = smem_u32(sA);
    uint32_t bBh = smem_u32(sBh);

    float ac[2][4][4];
#pragma unroll
    for (int i = 0; i < 2; i++)
#pragma unroll
        for (int j = 0; j < 4; j++)
#pragma unroll
            for (int q = 0; q < 4; q++) ac[i][j][q] = 0.0f;

    for (int c = 0; c < D_FF / 32; c++) {         // 64 chunks
        int k0 = c * 32;
        if (c > 0) __syncthreads();
        *(uint4*)dA       = *(const uint4*)(pA + k0);
        *(uint4*)(dA + 8) = *(const uint4*)(pA + k0 + 8);
        {
            const float* s = pB + (size_t)k0 * D_MODEL;
            float4 f0 = *(const float4*)s, f1 = *(const float4*)(s + 4);
            *dBh = cvt8h(f0, f1);
        }
        __syncthreads();

#pragma unroll
        for (int kk = 0; kk < 32; kk += 16) {
            uint32_t ah[2][4];
#pragma unroll
            for (int mf = 0; mf < 2; mf++) {
                uint32_t ro = wm * 32 + mf * 16 + (lane & 15);
                uint32_t co = kk + (lane >> 4) * 8;
                ldsm4(ah[mf], bA + (ro * SA + co) * 2);
            }
            uint32_t kr = kk + (lane & 7) + ((lane >> 4) & 1) * 8;
            uint32_t ncol = wn * 32 + ((lane >> 3) & 1) * 8;
            uint32_t bh[4][2], r4[4];
#pragma unroll
            for (int p = 0; p < 2; p++) {
                uint32_t off = (kr * SB + ncol + p * 16) * 2;
                ldsm4t(r4, bBh + off);
                bh[p*2][0] = r4[0]; bh[p*2+1][0] = r4[1]; bh[p*2][1] = r4[2]; bh[p*2+1][1] = r4[3];
            }
#pragma unroll
            for (int mf = 0; mf < 2; mf++)
#pragma unroll
                for (int nf = 0; nf < 4; nf++)
                    mma16816(ac[mf][nf], ah[mf], bh[nf][0], bh[nf][1]);
        }
    }

    // ---- epilogue: weighted atomic scatter-add ----
    int lr = lane >> 2, lc = (lane & 3) * 2;
#pragma unroll
    for (int mf = 0; mf < 2; mf++)
#pragma unroll
        for (int half = 0; half < 2; half++) {
            int slot = r0 + wm * 32 + mf * 16 + lr + half * 8;
            if (slot >= cnt) continue;
            int   tok = g_rows[e * CAP + slot];
            float w   = g_wts [e * CAP + slot];
            float* orow = out + (size_t)tok * D_MODEL + n0 + wn * 32 + lc;
#pragma unroll
            for (int nf = 0; nf < 4; nf++) {
                atomicAdd(&orow[nf * 8 + 0], ac[mf][nf][half * 2 + 0] * w);
                atomicAdd(&orow[nf * 8 + 1], ac[mf][nf][half * 2 + 1] * w);
            }
        }
}

// ======================= launch =======================
extern "C" void kernel_launch(void* const* d_in, const int* in_sizes, int n_in,
                              void* d_out, int out_size) {
    const float* x      = (const float*)d_in[0];   // [2,1024,768]
    const float* gate_w = (const float*)d_in[1];   // [768,8]
    const float* w_gate = (const float*)d_in[2];   // [8,768,2048]
    const float* w_up   = (const float*)d_in[3];   // [8,768,2048]
    const float* w_down = (const float*)d_in[4];   // [8,2048,768]
    float* out = (float*)d_out;

    k_reset<<<512, 256>>>(out, out_size);
    k_front<<<T_TOK / 8, 256>>>(x, gate_w);        // router + scatter + x->fp16

    {   // fused gate/up HMMA + SiLU
        dim3 grid(D_FF / 64, CAP / 128, NE);
        k_hmma_gu<<<grid, 256>>>(w_gate, w_up);
    }
    {   // down HMMA + weighted scatter-add
        dim3 grid(D_MODEL / 64, CAP / 128, NE);
        k_hmma_down<<<grid, 256>>>(w_down, out);
    }
}